// round 10
// baseline (speedup 1.0000x reference)
#include <cuda_runtime.h>

#define T_STEPS 2048
#define BATCH   256
#define HID     128
#define NTHREADS 512
#define HSW     144      // swizzled h stride per batch (128 + 4 pads)
#define GHS4    1544     // per-batch partial-array stride: 384*4 partials + 4 xhat + pad (16B-mult)

typedef unsigned long long u64;

__device__ __forceinline__ u64 ffma2(u64 a, u64 b, u64 c) {
    u64 d;
    asm("fma.rn.f32x2 %0, %1, %2, %3;" : "=l"(d) : "l"(a), "l"(b), "l"(c));
    return d;
}
__device__ __forceinline__ float hsum2(u64 v) {
    float x, y;
    asm("mov.b64 {%0, %1}, %2;" : "=f"(x), "=f"(y) : "l"(v));
    return x + y;
}

__global__ void __launch_bounds__(NTHREADS, 1)
gru_impute_kernel(const float* __restrict__ x,     // [B, T] (I=1)
                  const float* __restrict__ Wih,   // [384, 1]
                  const float* __restrict__ Whh,   // [384, 128]
                  const float* __restrict__ bih,   // [384]
                  const float* __restrict__ bhh,   // [384]
                  const float* __restrict__ Wfc,   // [1, 128]
                  const float* __restrict__ bfc,   // [1]
                  float* __restrict__ out)
{
    extern __shared__ float sm[];
    float* hsw   = sm;                 // 2 * HSW swizzled hidden state       (16B aligned)
    float* gh4   = sm + 2 * HSW;       // 2 * GHS4 per-slice gate partials    (16B aligned)
    float* wfcsw = gh4 + 2 * GHS4;     // 132: Wfc swizzled like h

    const int tid  = threadIdx.x;
    const int lane = tid & 31;
    const int wrp  = tid >> 5;         // 0..15
    const int ks   = lane & 3;         // k-slice 0..3 (32 k's each)
    const int g    = lane >> 2;        // row-in-group 0..7  (lane = 4g + ks)
    const int b0   = blockIdx.x * 2;
    const int r0   = wrp * 24 + g;

    // ---- one-time staging: Whh slices into registers (raw; ALL bias is in phase B) ----
    u64 wr0[16], wr1[16], wr2[16];
    {
        const u64* p0 = reinterpret_cast<const u64*>(Whh + (r0     ) * HID + ks * 32);
        const u64* p1 = reinterpret_cast<const u64*>(Whh + (r0 +  8) * HID + ks * 32);
        const u64* p2 = reinterpret_cast<const u64*>(Whh + (r0 + 16) * HID + ks * 32);
        #pragma unroll
        for (int i = 0; i < 16; ++i) { wr0[i] = __ldg(p0 + i); wr1[i] = __ldg(p1 + i); wr2[i] = __ldg(p2 + i); }
    }
    for (int idx = tid; idx < 2 * HSW; idx += NTHREADS) hsw[idx] = 0.0f;
    if (tid < 4) { gh4[1536 + tid] = 0.0f; gh4[GHS4 + 1536 + tid] = 0.0f; }
    for (int idx = tid; idx < HID; idx += NTHREADS)
        wfcsw[idx + (idx >> 5) * 4] = Wfc[idx];

    // ---- B-phase per-thread constants (threads 0..255) ----
    const int ub = tid & 127;
    const int b  = tid >> 7;           // batch for B threads
    float wih_r = 0.f, wih_z = 0.f, wih_n = 0.f, br = 0.f, bz = 0.f, bnI = 0.f, bhn = 0.f, bf = 0.f;
    float xn = 0.f;
    if (tid < 256) {
        wih_r = Wih[ub];        br  = bih[ub]       + bhh[ub];
        wih_z = Wih[ub + 128];  bz  = bih[ub + 128] + bhh[ub + 128];
        wih_n = Wih[ub + 256];  bnI = bih[ub + 256];
        bhn   = bhh[ub + 256];
        bf    = bfc[0];
        xn    = __ldg(x + (size_t)(b0 + b) * T_STEPS);
    }
    __syncthreads();

    const ulonglong2* hb0 = reinterpret_cast<const ulonglong2*>(hsw + ks * 36);
    const ulonglong2* hb1 = reinterpret_cast<const ulonglong2*>(hsw + HSW + ks * 36);
    float* pa0 = gh4 + wrp * 96 + lane;            // batch-0 partial base for this lane (= 4*row + ks)
    float* pa1 = pa0 + GHS4;                       // batch-1

    float* newin = out;                            // [T, B]
    float* pred  = out + T_STEPS * BATCH;          // [B, T-1]

    for (int t = 0; t < T_STEPS; ++t) {
        // ================= Phase A: raw matvec partials, all 16 warps =================
        {
            u64 q0 = 0ull, q1 = 0ull, q2 = 0ull;
            #pragma unroll
            for (int c = 0; c < 8; ++c) {
                ulonglong2 hv = hb0[c];
                q0 = ffma2(wr0[2 * c],     hv.x, q0);
                q1 = ffma2(wr1[2 * c],     hv.x, q1);
                q2 = ffma2(wr2[2 * c],     hv.x, q2);
                q0 = ffma2(wr0[2 * c + 1], hv.y, q0);
                q1 = ffma2(wr1[2 * c + 1], hv.y, q1);
                q2 = ffma2(wr2[2 * c + 1], hv.y, q2);
            }
            pa0[0]  = hsum2(q0);                   // partial of row r0,    slice ks
            pa0[32] = hsum2(q1);                   // row r0+8
            pa0[64] = hsum2(q2);                   // row r0+16
        }
        {
            u64 q0 = 0ull, q1 = 0ull, q2 = 0ull;
            #pragma unroll
            for (int c = 0; c < 8; ++c) {
                ulonglong2 hv = hb1[c];
                q0 = ffma2(wr0[2 * c],     hv.x, q0);
                q1 = ffma2(wr1[2 * c],     hv.x, q1);
                q2 = ffma2(wr2[2 * c],     hv.x, q2);
                q0 = ffma2(wr0[2 * c + 1], hv.y, q0);
                q1 = ffma2(wr1[2 * c + 1], hv.y, q1);
                q2 = ffma2(wr2[2 * c + 1], hv.y, q2);
            }
            pa1[0]  = hsum2(q0);
            pa1[32] = hsum2(q1);
            pa1[64] = hsum2(q2);
        }
        // x_hat row (Wfc . h(t-1)) — warp 0, lanes 0..3 only
        if (wrp == 0 && g == 0) {
            const ulonglong2* wfcp = reinterpret_cast<const ulonglong2*>(wfcsw + ks * 36);
            u64 q3 = 0ull;
            #pragma unroll
            for (int c = 0; c < 8; ++c) {
                ulonglong2 wv = wfcp[c]; ulonglong2 hv = hb0[c];
                q3 = ffma2(wv.x, hv.x, q3);
                q3 = ffma2(wv.y, hv.y, q3);
            }
            gh4[1536 + ks] = hsum2(q3);
            q3 = 0ull;
            #pragma unroll
            for (int c = 0; c < 8; ++c) {
                ulonglong2 wv = wfcp[c]; ulonglong2 hv = hb1[c];
                q3 = ffma2(wv.x, hv.x, q3);
                q3 = ffma2(wv.y, hv.y, q3);
            }
            gh4[GHS4 + 1536 + ks] = hsum2(q3);
        }
        __syncthreads();

        // ================= Phase B: gates + update, threads 0..255 =================
        if (tid < 256) {
            const float* g4 = gh4 + b * GHS4;
            float4 pr = *reinterpret_cast<const float4*>(g4 + ub * 4);
            float4 pz = *reinterpret_cast<const float4*>(g4 + 512 + ub * 4);
            float4 pn = *reinterpret_cast<const float4*>(g4 + 1024 + ub * 4);
            float4 xq = *reinterpret_cast<const float4*>(g4 + 1536);
            float xh = (xq.x + xq.y) + (xq.z + xq.w) + bf;

            float xt = xn;
            if (t + 1 < T_STEPS)
                xn = __ldg(x + (size_t)(b0 + b) * T_STEPS + t + 1);

            float cur = (t == 0) ? xt : ((xt == 128.0f) ? xh : xt);

            float sr = (pr.x + pr.y) + (pr.z + pr.w);
            float sz = (pz.x + pz.y) + (pz.z + pz.w);
            float sn = (pn.x + pn.y) + (pn.z + pn.w);

            float gr = fmaf(cur, wih_r, br) + sr;
            float gz = fmaf(cur, wih_z, bz) + sz;
            float gni = fmaf(cur, wih_n, bnI);

            float r  = __fdividef(1.0f, 1.0f + __expf(-gr));
            float z  = __fdividef(1.0f, 1.0f + __expf(-gz));
            float na = fmaf(r, sn + bhn, gni);
            float e2 = __expf(2.0f * na);
            float n  = 1.0f - __fdividef(2.0f, e2 + 1.0f);   // tanh

            const int hidx = b * HSW + ub + (ub >> 5) * 4;   // swizzled h index
            float hold = hsw[hidx];
            float hnew = fmaf(z, hold - n, n);
            hsw[hidx] = hnew;

            if (ub == 0) {
                newin[t * BATCH + b0 + b] = cur;
                if (t > 0) pred[(size_t)(b0 + b) * (T_STEPS - 1) + (t - 1)] = xh;
            }
        }
        __syncthreads();
    }
}

extern "C" void kernel_launch(void* const* d_in, const int* in_sizes, int n_in,
                              void* d_out, int out_size)
{
    (void)in_sizes; (void)n_in; (void)out_size;
    const float* x    = (const float*)d_in[0];
    const float* Wih  = (const float*)d_in[1];
    const float* Whh  = (const float*)d_in[2];
    const float* bih  = (const float*)d_in[3];
    const float* bhh  = (const float*)d_in[4];
    const float* Wfc  = (const float*)d_in[5];
    const float* bfc  = (const float*)d_in[6];
    float* out = (float*)d_out;

    const size_t smem = (size_t)(2 * HSW + 2 * GHS4 + 132 + 4) * sizeof(float);
    cudaFuncSetAttribute(gru_impute_kernel, cudaFuncAttributeMaxDynamicSharedMemorySize, (int)smem);

    gru_impute_kernel<<<BATCH / 2, NTHREADS, smem>>>(x, Wih, Whh, bih, bhh, Wfc, bfc, out);
}

// round 11
// speedup vs baseline: 2.2915x; 2.2915x over previous
#include <cuda_runtime.h>

#define T_STEPS 2048
#define BATCH   256
#define HID     128
#define NTHREADS 512
#define GHS     392      // ghs row stride (floats); slot 384 = x_hat
#define HSW     144      // swizzled h stride per batch (128 + 4 pads)

typedef unsigned long long u64;

__device__ __forceinline__ u64 ffma2(u64 a, u64 b, u64 c) {
    u64 d;
    asm("fma.rn.f32x2 %0, %1, %2, %3;" : "=l"(d) : "l"(a), "l"(b), "l"(c));
    return d;
}
__device__ __forceinline__ float hsum2(u64 v) {
    float x, y;
    asm("mov.b64 {%0, %1}, %2;" : "=f"(x), "=f"(y) : "l"(v));
    return x + y;
}

__global__ void __launch_bounds__(NTHREADS, 1)
gru_impute_kernel(const float* __restrict__ x,     // [B, T] (I=1)
                  const float* __restrict__ Wih,   // [384, 1]
                  const float* __restrict__ Whh,   // [384, 128]
                  const float* __restrict__ bih,   // [384]
                  const float* __restrict__ bhh,   // [384]
                  const float* __restrict__ Wfc,   // [1, 128]
                  const float* __restrict__ bfc,   // [1]
                  float* __restrict__ out)
{
    extern __shared__ float sm[];
    float* hsw   = sm;                 // 2 * HSW swizzled hidden state (16B aligned)
    float* ghs   = sm + 2 * HSW;       // 2 * GHS raw gate dots + x_hat slot
    float* wfcsw = ghs + 2 * GHS;      // 132: Wfc swizzled like h

    const int tid  = threadIdx.x;
    const int lane = tid & 31;
    const int wrp  = tid >> 5;         // 0..15
    const int ks   = lane & 3;         // k-slice 0..3 (32 k's each)
    const int g    = lane >> 2;        // row-in-group 0..7
    const int b0   = blockIdx.x * 2;
    const int r0   = wrp * 24 + g;

    // ---- one-time staging: Whh slices into registers (raw dots; all bias in B) ----
    u64 wr0[16], wr1[16], wr2[16];
    {
        const u64* p0 = reinterpret_cast<const u64*>(Whh + (r0     ) * HID + ks * 32);
        const u64* p1 = reinterpret_cast<const u64*>(Whh + (r0 +  8) * HID + ks * 32);
        const u64* p2 = reinterpret_cast<const u64*>(Whh + (r0 + 16) * HID + ks * 32);
        #pragma unroll
        for (int i = 0; i < 16; ++i) { wr0[i] = __ldg(p0 + i); wr1[i] = __ldg(p1 + i); wr2[i] = __ldg(p2 + i); }
    }
    for (int idx = tid; idx < 2 * HSW; idx += NTHREADS) hsw[idx] = 0.0f;
    if (tid == 0) { ghs[384] = 0.0f; ghs[GHS + 384] = 0.0f; }
    for (int idx = tid; idx < HID; idx += NTHREADS)
        wfcsw[idx + (idx >> 5) * 4] = Wfc[idx];

    // ---- B-phase per-thread constants (threads 0..255) ----
    const int ub = tid & 127;
    const int b  = tid >> 7;
    float wih_r = 0.f, wih_z = 0.f, wih_n = 0.f, br = 0.f, bz = 0.f, bnI = 0.f, bhn = 0.f, bf = 0.f;
    float xn = 0.f;
    if (tid < 256) {
        wih_r = Wih[ub];        br  = bih[ub]       + bhh[ub];
        wih_z = Wih[ub + 128];  bz  = bih[ub + 128] + bhh[ub + 128];
        wih_n = Wih[ub + 256];  bnI = bih[ub + 256];
        bhn   = bhh[ub + 256];
        bf    = bfc[0];
        xn    = __ldg(x + (size_t)(b0 + b) * T_STEPS);
    }
    __syncthreads();

    const ulonglong2* hb0 = reinterpret_cast<const ulonglong2*>(hsw + ks * 36);
    const ulonglong2* hb1 = reinterpret_cast<const ulonglong2*>(hsw + HSW + ks * 36);
    const ulonglong2* wfcp = reinterpret_cast<const ulonglong2*>(wfcsw + ks * 36);
    float* paA0 = ghs + r0 + 8 * ks;           // store slot, ks<3 (R8-validated mapping)
    float* paA1 = paA0 + GHS;
    // this warp's x_hat duty: warp 0 -> batch 0, warp 1 -> batch 1 (lanes 0..3 only)
    const bool xduty = (wrp < 2) && (g == 0);
    const ulonglong2* hbx = (wrp == 0) ? hb0 : hb1;
    float* xslot = ghs + (wrp == 0 ? 0 : GHS) + 384;

    float* newin = out;                            // [T, B]
    float* pred  = out + T_STEPS * BATCH;          // [B, T-1]

    for (int t = 0; t < T_STEPS; ++t) {
        // ================= Phase A: matvec, all 16 warps =================
        {
            u64 q0 = 0ull, q1 = 0ull, q2 = 0ull;
            #pragma unroll
            for (int c = 0; c < 8; ++c) {
                ulonglong2 hv = hb0[c];
                q0 = ffma2(wr0[2 * c],     hv.x, q0);
                q1 = ffma2(wr1[2 * c],     hv.x, q1);
                q2 = ffma2(wr2[2 * c],     hv.x, q2);
                q0 = ffma2(wr0[2 * c + 1], hv.y, q0);
                q1 = ffma2(wr1[2 * c + 1], hv.y, q1);
                q2 = ffma2(wr2[2 * c + 1], hv.y, q2);
            }
            float f0 = hsum2(q0), f1 = hsum2(q1), f2 = hsum2(q2);
            float snd = (ks & 1) ? f0 : f1;
            float kp  = (ks & 1) ? f1 : f0;
            float av  = kp + __shfl_xor_sync(0xffffffffu, snd, 1);
            float cv  = f2 + __shfl_xor_sync(0xffffffffu, f2, 1);
            float resA = av + __shfl_xor_sync(0xffffffffu, av, 2);
            float resC = cv + __shfl_xor_sync(0xffffffffu, cv, 2);
            if (ks < 3) paA0[0] = (ks < 2) ? resA : resC;
        }
        {
            u64 q0 = 0ull, q1 = 0ull, q2 = 0ull;
            #pragma unroll
            for (int c = 0; c < 8; ++c) {
                ulonglong2 hv = hb1[c];
                q0 = ffma2(wr0[2 * c],     hv.x, q0);
                q1 = ffma2(wr1[2 * c],     hv.x, q1);
                q2 = ffma2(wr2[2 * c],     hv.x, q2);
                q0 = ffma2(wr0[2 * c + 1], hv.y, q0);
                q1 = ffma2(wr1[2 * c + 1], hv.y, q1);
                q2 = ffma2(wr2[2 * c + 1], hv.y, q2);
            }
            float f0 = hsum2(q0), f1 = hsum2(q1), f2 = hsum2(q2);
            float snd = (ks & 1) ? f0 : f1;
            float kp  = (ks & 1) ? f1 : f0;
            float av  = kp + __shfl_xor_sync(0xffffffffu, snd, 1);
            float cv  = f2 + __shfl_xor_sync(0xffffffffu, f2, 1);
            float resA = av + __shfl_xor_sync(0xffffffffu, av, 2);
            float resC = cv + __shfl_xor_sync(0xffffffffu, cv, 2);
            if (ks < 3) paA1[0] = (ks < 2) ? resA : resC;
        }
        // x_hat = Wfc . h(t-1): warp 0 (batch 0) / warp 1 (batch 1), lanes 0..3
        if (xduty) {
            u64 q3 = 0ull;
            #pragma unroll
            for (int c = 0; c < 8; ++c) {
                ulonglong2 wv = wfcp[c]; ulonglong2 hv = hbx[c];
                q3 = ffma2(wv.x, hv.x, q3);
                q3 = ffma2(wv.y, hv.y, q3);
            }
            float f = hsum2(q3);
            f += __shfl_xor_sync(0x0000000Fu, f, 1);
            f += __shfl_xor_sync(0x0000000Fu, f, 2);
            if (ks == 0) xslot[0] = f;
        }
        __syncthreads();

        // ================= Phase B: gates + update, threads 0..255 =================
        if (tid < 256) {
            const float* gh = ghs + b * GHS;
            float xh = gh[384] + bf;

            float xt = xn;
            if (t + 1 < T_STEPS)
                xn = __ldg(x + (size_t)(b0 + b) * T_STEPS + t + 1);

            float cur = (t == 0) ? xt : ((xt == 128.0f) ? xh : xt);

            float gr  = fmaf(cur, wih_r, br) + gh[ub];
            float gz  = fmaf(cur, wih_z, bz) + gh[ub + 128];
            float gni = fmaf(cur, wih_n, bnI);

            float r  = __fdividef(1.0f, 1.0f + __expf(-gr));
            float z  = __fdividef(1.0f, 1.0f + __expf(-gz));
            float na = fmaf(r, gh[ub + 256] + bhn, gni);
            float e2 = __expf(2.0f * na);
            float n  = 1.0f - __fdividef(2.0f, e2 + 1.0f);   // tanh

            const int hidx = b * HSW + ub + (ub >> 5) * 4;   // swizzled h index
            float hold = hsw[hidx];
            float hnew = fmaf(z, hold - n, n);
            hsw[hidx] = hnew;

            if (ub == 0) {
                newin[t * BATCH + b0 + b] = cur;
                if (t > 0) pred[(size_t)(b0 + b) * (T_STEPS - 1) + (t - 1)] = xh;
            }
        }
        __syncthreads();
    }
}

extern "C" void kernel_launch(void* const* d_in, const int* in_sizes, int n_in,
                              void* d_out, int out_size)
{
    (void)in_sizes; (void)n_in; (void)out_size;
    const float* x    = (const float*)d_in[0];
    const float* Wih  = (const float*)d_in[1];
    const float* Whh  = (const float*)d_in[2];
    const float* bih  = (const float*)d_in[3];
    const float* bhh  = (const float*)d_in[4];
    const float* Wfc  = (const float*)d_in[5];
    const float* bfc  = (const float*)d_in[6];
    float* out = (float*)d_out;

    const size_t smem = (size_t)(2 * HSW + 2 * GHS + 132 + 4) * sizeof(float);
    cudaFuncSetAttribute(gru_impute_kernel, cudaFuncAttributeMaxDynamicSharedMemorySize, (int)smem);

    gru_impute_kernel<<<BATCH / 2, NTHREADS, smem>>>(x, Wih, Whh, bih, bhh, Wfc, bfc, out);
}